// round 1
// baseline (speedup 1.0000x reference)
#include <cuda_runtime.h>
#include <math.h>

#define B_  2
#define T_  2048
#define C_  1024
#define H_  16
#define HD  64
#define BT  (B_*T_)      // 4096
#define C5  (5*C_)       // 5120
#define NC  (T_/HD)      // 32 chunks
#define BH  (B_*H_)      // 32

// ---------------- scratch (device globals; no allocations allowed) ----------------
__device__ float g_xn   [BT*(size_t)C_];     // rmsnormed x            16MB
__device__ float g_qkvff[BT*(size_t)C5];     // qkvff                  80MB
__device__ float g_W    [BH*(size_t)NC*HD*HD]; // chunk KV summaries   16MB
__device__ float g_S    [BH*(size_t)NC*HD*HD]; // scanned states       16MB
__device__ float g_y    [BT*(size_t)C_];     // attention out / GN'd   16MB
__device__ float g_y2   [BT*(size_t)C_];     // gated                  16MB
__device__ float g_yp   [BT*(size_t)C_];     // proj out               16MB
__device__ float g_ffg  [BT*(size_t)2*C_];   // gelu(ff)               32MB

// ---------------- K1: RMSNorm ----------------
__global__ void k_rmsnorm(const float* __restrict__ x, const float* __restrict__ rms_w) {
    int n = blockIdx.x;
    const float* xr = x + (size_t)n*C_;
    __shared__ float red[256];
    float s = 0.f;
    for (int c = threadIdx.x; c < C_; c += 256) { float v = xr[c]; s += v*v; }
    red[threadIdx.x] = s; __syncthreads();
    for (int o = 128; o > 0; o >>= 1) {
        if (threadIdx.x < o) red[threadIdx.x] += red[threadIdx.x+o];
        __syncthreads();
    }
    float nrm = sqrtf(red[0]) * 0.03125f;           // * C^-0.5 (1/32 exact)
    float inv = 1.0f / fmaxf(nrm, 1e-8f);
    for (int c = threadIdx.x; c < C_; c += 256)
        g_xn[(size_t)n*C_ + c] = xr[c]*inv*rms_w[c];
}

// ---------------- generic NT SGEMM: C[M,N] = A[M,K] * B[N,K]^T + epilogue ----------------
// EPI 0: plain   1: silu(acc+bias[n])*aux0   2: acc+bias[n]   3: acc+aux0+aux1
template<int EPI>
__global__ void __launch_bounds__(256) sgemm_nt(
    const float* __restrict__ A, const float* __restrict__ Bm, float* __restrict__ Cm,
    int M, int N, int K,
    const float* __restrict__ bias, const float* __restrict__ aux0, const float* __restrict__ aux1)
{
    __shared__ __align__(16) float As[32][68];
    __shared__ __align__(16) float Bs[32][68];
    int tid = threadIdx.x;
    int tx = tid & 15, ty = tid >> 4;
    int bm = blockIdx.y << 6, bn = blockIdx.x << 6;
    const float* Ab = A  + (size_t)bm*K;
    const float* Bb = Bm + (size_t)bn*K;
    float acc[4][4];
    #pragma unroll
    for (int i = 0; i < 4; i++)
        #pragma unroll
        for (int j = 0; j < 4; j++) acc[i][j] = 0.f;

    for (int k0 = 0; k0 < K; k0 += 32) {
        #pragma unroll
        for (int r = 0; r < 8; r++) {
            int idx = tid + (r << 8);
            int m = idx >> 5, k = idx & 31;
            As[k][m] = Ab[(size_t)m*K + k0 + k];
            Bs[k][m] = Bb[(size_t)m*K + k0 + k];
        }
        __syncthreads();
        #pragma unroll
        for (int kk = 0; kk < 32; kk++) {
            float4 av = *(const float4*)&As[kk][ty << 2];
            float4 bv = *(const float4*)&Bs[kk][tx << 2];
            float a[4] = {av.x, av.y, av.z, av.w};
            float b[4] = {bv.x, bv.y, bv.z, bv.w};
            #pragma unroll
            for (int i = 0; i < 4; i++)
                #pragma unroll
                for (int j = 0; j < 4; j++)
                    acc[i][j] += a[i]*b[j];
        }
        __syncthreads();
    }
    #pragma unroll
    for (int i = 0; i < 4; i++) {
        int m = bm + (ty << 2) + i;
        #pragma unroll
        for (int j = 0; j < 4; j++) {
            int n = bn + (tx << 2) + j;
            float v = acc[i][j];
            size_t o = (size_t)m*N + n;
            if (EPI == 1) { float z = v + bias[n]; v = (z/(1.f + expf(-z))) * aux0[o]; }
            else if (EPI == 2) { v += bias[n]; }
            else if (EPI == 3) { v += aux0[o] + aux1[o]; }
            Cm[o] = v;
        }
    }
}

// ---------------- K3: xPos rotary on q (scale) and k (1/scale), in place ----------------
__global__ void k_xpos() {
    int idx = blockIdx.x*256 + threadIdx.x;          // over BT*512 pairs
    int n = idx >> 9;
    int j = idx & 511;
    int t = n & (T_-1);
    // match reference fp32 angle, then exact sin/cos of that value
    float invf  = powf(10000.0f, -(float)j/512.0f);
    float theta = (float)t * invf;
    double sd, cd;
    sincos((double)theta, &sd, &cd);
    float svec  = (2.0f*(float)j + 0.4f*1024.0f) / (1.4f*1024.0f);
    float pw    = ((float)t - 1024.0f) * (1.0f/512.0f);
    float scale = powf(svec, pw);
    float cs = (float)cd, sn = (float)sd;
    float cq = cs*scale,  sq = sn*scale;
    float ck = cs/scale,  sk = sn/scale;
    float* q = g_qkvff + (size_t)n*C5 + 2*j;
    float* k = q + C_;
    float q0 = q[0], q1 = q[1];
    q[0] = q0*cq - q1*sq;  q[1] = q1*cq + q0*sq;
    float k0 = k[0], k1 = k[1];
    k[0] = k0*ck - k1*sk;  k[1] = k1*ck + k0*sk;
}

// ---------------- K4: per-chunk KV summary  W_c = sum_j gamma^(64-j) k_j v_j^T ----------------
__global__ void k_chunk_kv() {
    int blk = blockIdx.x;            // BH*NC blocks
    int bh = blk / NC, c = blk % NC;
    int b = bh / H_,   h = bh % H_;
    float gamma = 1.0f - exp2f(-5.0f - (float)h);
    __shared__ float Ks[64*65], Vs[64*65], dec[64];
    for (int i = threadIdx.x; i < HD*HD; i += 256) {
        int j = i >> 6, d = i & 63;
        size_t base = (size_t)(b*T_ + c*HD + j)*C5 + h*HD + d;
        Ks[j*65+d] = g_qkvff[base + C_];
        Vs[j*65+d] = g_qkvff[base + 2*C_];
    }
    if (threadIdx.x < 64) dec[threadIdx.x] = powf(gamma, (float)(HD - threadIdx.x));
    __syncthreads();
    float* Wout = g_W + ((size_t)bh*NC + c)*HD*HD;
    for (int i = threadIdx.x; i < HD*HD; i += 256) {
        int d = i >> 6, e = i & 63;
        float s = 0.f;
        #pragma unroll 8
        for (int j = 0; j < 64; j++) s += dec[j]*Ks[j*65+d]*Vs[j*65+e];
        Wout[i] = s;
    }
}

// ---------------- K5: state scan  S_{c+1} = gamma^64 * S_c + W_c ----------------
__global__ void k_scan() {
    int bh = blockIdx.x;             // BH blocks, 256 threads, 16 state elems/thread
    int h = bh % H_;
    float gamma = 1.0f - exp2f(-5.0f - (float)h);
    float g64 = powf(gamma, 64.0f);
    float st[16];
    #pragma unroll
    for (int r = 0; r < 16; r++) st[r] = 0.f;
    size_t base0 = (size_t)bh*NC*4096;
    for (int c = 0; c < NC; c++) {
        size_t base = base0 + (size_t)c*4096;
        #pragma unroll
        for (int r = 0; r < 16; r++) {
            int i = threadIdx.x + r*256;
            g_S[base + i] = st[r];
            st[r] = st[r]*g64 + g_W[base + i];
        }
    }
}

// ---------------- K6: per-chunk attention  Y = mask(QK^T)V + gamma^i * Q S_c, * hd^-0.5 --------
__global__ void k_chunk_attn() {
    extern __shared__ float sm[];
    float* Qs = sm;
    float* Ks = Qs + 64*65;
    float* Vs = Ks + 64*65;
    float* Ss = Vs + 64*65;
    float* As = Ss + 64*65;
    int blk = blockIdx.x;            // BH*NC
    int bh = blk / NC, c = blk % NC;
    int b = bh / H_,   h = bh % H_;
    float gamma = 1.0f - exp2f(-5.0f - (float)h);
    for (int i = threadIdx.x; i < 4096; i += 256) {
        int j = i >> 6, d = i & 63;
        size_t base = (size_t)(b*T_ + c*HD + j)*C5 + h*HD + d;
        Qs[j*65+d] = g_qkvff[base];
        Ks[j*65+d] = g_qkvff[base + C_];
        Vs[j*65+d] = g_qkvff[base + 2*C_];
        Ss[j*65+d] = g_S[((size_t)bh*NC + c)*4096 + i];
    }
    __syncthreads();
    for (int p = threadIdx.x; p < 4096; p += 256) {
        int i = p >> 6, j = p & 63;
        float s = 0.f;
        if (j <= i) {
            #pragma unroll 8
            for (int d = 0; d < 64; d++) s += Qs[i*65+d]*Ks[j*65+d];
            s *= powf(gamma, (float)(i - j));
        }
        As[i*65+j] = s;
    }
    __syncthreads();
    for (int p = threadIdx.x; p < 4096; p += 256) {
        int i = p >> 6, e = p & 63;
        float acc = 0.f, cr = 0.f;
        #pragma unroll 8
        for (int j = 0; j < 64; j++) {
            acc += As[i*65+j]*Vs[j*65+e];
            cr  += Qs[i*65+j]*Ss[j*65+e];
        }
        acc += powf(gamma, (float)i)*cr;
        g_y[(size_t)(b*T_ + c*HD + i)*C_ + h*HD + e] = acc * 0.125f;  // hd^-0.5
    }
}

// ---------------- K7: GroupNorm per (b,t,h) over hd=64, then affine by gn_w/gn_b ----------------
__global__ void k_gn(const float* __restrict__ gn_w, const float* __restrict__ gn_b) {
    int row = blockIdx.x;            // BT*H rows
    int d = threadIdx.x;             // 32 threads
    float* yr = g_y + (size_t)row*64;
    float a = yr[d], b2 = yr[d+32];
    float s = a + b2;
    #pragma unroll
    for (int o = 16; o; o >>= 1) s += __shfl_xor_sync(~0u, s, o);
    float mu = s * (1.0f/64.0f);
    float da = a - mu, db = b2 - mu;
    float ss = da*da + db*db;
    #pragma unroll
    for (int o = 16; o; o >>= 1) ss += __shfl_xor_sync(~0u, ss, o);
    float inv = rsqrtf(ss*(1.0f/64.0f) + 1e-5f);
    int cb = (row & 15)*64;
    yr[d]    = da*inv*gn_w[cb+d]    + gn_b[cb+d];
    yr[d+32] = db*inv*gn_w[cb+d+32] + gn_b[cb+d+32];
}

// ---------------- K10: exact GELU on ff slice ----------------
__global__ void k_gelu() {
    int idx = blockIdx.x*256 + threadIdx.x;     // over BT*2C
    int n = idx / (2*C_);
    int e = idx - n*(2*C_);
    float v = g_qkvff[(size_t)n*C5 + 3*C_ + e];
    g_ffg[idx] = 0.5f*v*(1.0f + erff(v*0.70710678118654752f));
}

// ---------------- launch ----------------
extern "C" void kernel_launch(void* const* d_in, const int* in_sizes, int n_in,
                              void* d_out, int out_size) {
    const float* x       = (const float*)d_in[0];
    const float* w_qkvff = (const float*)d_in[1];
    const float* w_gated = (const float*)d_in[2];
    const float* b_gated = (const float*)d_in[3];
    const float* w_proj  = (const float*)d_in[4];
    const float* b_proj  = (const float*)d_in[5];
    const float* gn_w    = (const float*)d_in[6];
    const float* gn_b    = (const float*)d_in[7];
    const float* w_ff    = (const float*)d_in[8];
    const float* rms_w   = (const float*)d_in[9];
    float* out = (float*)d_out;

    float *p_xn, *p_qkvff, *p_y, *p_y2, *p_yp, *p_ffg;
    cudaGetSymbolAddress((void**)&p_xn,    g_xn);
    cudaGetSymbolAddress((void**)&p_qkvff, g_qkvff);
    cudaGetSymbolAddress((void**)&p_y,     g_y);
    cudaGetSymbolAddress((void**)&p_y2,    g_y2);
    cudaGetSymbolAddress((void**)&p_yp,    g_yp);
    cudaGetSymbolAddress((void**)&p_ffg,   g_ffg);

    cudaFuncSetAttribute(k_chunk_attn, cudaFuncAttributeMaxDynamicSharedMemorySize, 5*64*65*4);

    // 1. RMSNorm
    k_rmsnorm<<<BT, 256>>>(x, rms_w);
    // 2. qkvff = xn @ w_qkvff^T   [4096 x 5120 x 1024]
    sgemm_nt<0><<<dim3(C5/64, BT/64), 256>>>(p_xn, w_qkvff, p_qkvff, BT, C5, C_,
                                             nullptr, nullptr, nullptr);
    // 3. xPos on q, k (in place)
    k_xpos<<<(BT*512)/256, 256>>>();
    // 4-6. chunked retention
    k_chunk_kv<<<BH*NC, 256>>>();
    k_scan<<<BH, 256>>>();
    k_chunk_attn<<<BH*NC, 256, 5*64*65*4>>>();
    // 7. GroupNorm
    k_gn<<<BT*H_, 32>>>(gn_w, gn_b);
    // 8. gate: y2 = silu(x @ w_gated^T + b) * y_gn
    sgemm_nt<1><<<dim3(C_/64, BT/64), 256>>>(x, w_gated, p_y2, BT, C_, C_,
                                             b_gated, p_y, nullptr);
    // 9. proj: yp = y2 @ w_proj^T + b_proj
    sgemm_nt<2><<<dim3(C_/64, BT/64), 256>>>(p_y2, w_proj, p_yp, BT, C_, C_,
                                             b_proj, nullptr, nullptr);
    // 10. gelu(ff)
    k_gelu<<<(BT*2*C_)/256, 256>>>();
    // 11. out = gelu(ff) @ w_ff^T + x + yp
    sgemm_nt<3><<<dim3(C_/64, BT/64), 256>>>(p_ffg, w_ff, out, BT, C_, 2*C_,
                                             nullptr, x, p_yp);
}

// round 3
// speedup vs baseline: 2.4140x; 2.4140x over previous
#include <cuda_runtime.h>
#include <cuda_bf16.h>
#include <math.h>
#include <stdint.h>

#define B_  2
#define T_  2048
#define C_  1024
#define H_  16
#define HD  64
#define BT  (B_*T_)      // 4096
#define C5  (5*C_)       // 5120
#define NC  (T_/HD)      // 32 chunks
#define BH  (B_*H_)      // 32

// ---------------- scratch (device globals) ----------------
__device__ float g_qkvff[BT*(size_t)C5];          // qkvff fp32 (attn + gelu src)
__device__ float g_W [BH*(size_t)NC*HD*HD];
__device__ float g_S [BH*(size_t)NC*HD*HD];
__device__ float g_y [BT*(size_t)C_];             // attn out -> GN'd
__device__ float g_yp[BT*(size_t)C_];             // proj out
// split-bf16 GEMM operands (A: [hi|lo|hi], B: [hi|hi|lo] along K' = 3K)
__device__ __nv_bfloat16 g_a_qkv [BT*(size_t)3*C_];
__device__ __nv_bfloat16 g_b_qkv [C5*(size_t)3*C_];
__device__ __nv_bfloat16 g_a_x   [BT*(size_t)3*C_];
__device__ __nv_bfloat16 g_b_gat [C_*(size_t)3*C_];
__device__ __nv_bfloat16 g_a_prj [BT*(size_t)3*C_];   // split(silu-gated y2)
__device__ __nv_bfloat16 g_b_prj [C_*(size_t)3*C_];
__device__ __nv_bfloat16 g_a_ff  [BT*(size_t)6*C_];   // split(gelu(ff)), K=2048
__device__ __nv_bfloat16 g_b_ff  [C_*(size_t)6*C_];

// ---------------- PTX helpers ----------------
__device__ __forceinline__ uint32_t smem_u32(const void* p) {
    uint32_t a;
    asm("{ .reg .u64 t; cvta.to.shared.u64 t, %1; cvt.u32.u64 %0, t; }" : "=r"(a) : "l"(p));
    return a;
}
#define CPA(dst, src)  asm volatile("cp.async.cg.shared.global [%0], [%1], 16;" :: "r"(dst), "l"(src) : "memory")
#define CPC()          asm volatile("cp.async.commit_group;" ::: "memory")
#define CPW(n)         asm volatile("cp.async.wait_group %0;" :: "n"(n) : "memory")
#define SWZ(o) ((o) ^ (((o) >> 3) & 0x70))

#define LDM_X4(r0, r1, r2, r3, a) \
    asm volatile("ldmatrix.sync.aligned.m8n8.x4.shared.b16 {%0,%1,%2,%3}, [%4];" \
        : "=r"(r0), "=r"(r1), "=r"(r2), "=r"(r3) : "r"(a))

#define MMA_BF16(d, a, b0, b1) \
    asm volatile("mma.sync.aligned.m16n8k16.row.col.f32.bf16.bf16.f32 " \
        "{%0,%1,%2,%3}, {%4,%5,%6,%7}, {%8,%9}, {%0,%1,%2,%3};" \
        : "+f"((d)[0]), "+f"((d)[1]), "+f"((d)[2]), "+f"((d)[3]) \
        : "r"((a)[0]), "r"((a)[1]), "r"((a)[2]), "r"((a)[3]), "r"(b0), "r"(b1))

// ---------------- warp-MMA split-bf16 NT GEMM ----------------
// C[M=BT, N] = A'[M, Kp] * B'[N, Kp]^T   (Kp = 3K split encoding)
// tile 128x128, BK=64, 4-stage cp.async pipeline, 8 warps (4 m x 2 n), warp 32x64
// EPI 0: Cout=v    1: silu(v+bias[n])*aux0 -> split-bf16 osplit (K=1024)
// EPI 2: v+bias[n] 3: v+aux0+aux1
template<int EPI>
__global__ void __launch_bounds__(256, 1) mma_gemm(
    const __nv_bfloat16* __restrict__ A, const __nv_bfloat16* __restrict__ Bm,
    int Kp, int N, float* __restrict__ Cout,
    const float* __restrict__ bias, const float* __restrict__ aux0,
    const float* __restrict__ aux1, __nv_bfloat16* __restrict__ osplit)
{
    extern __shared__ __align__(1024) char smem_raw[];
    const int S = 4;
    uint32_t sbase = (smem_u32(smem_raw) + 1023) & ~1023u;

    int tid = threadIdx.x;
    int wid = tid >> 5, lane = tid & 31;
    int warp_m = wid & 3, warp_n = wid >> 2;
    int bm = blockIdx.y << 7, bn = blockIdx.x << 7;

    const int nk = Kp >> 6;

    auto load_stage = [&](int s, int k) {
        uint32_t a_s = sbase + s * 32768u;
        uint32_t b_s = a_s + 16384u;
        const __nv_bfloat16* Ag = A + (size_t)bm * Kp + (size_t)k * 64;
        const __nv_bfloat16* Bg = Bm + (size_t)bn * Kp + (size_t)k * 64;
        #pragma unroll
        for (int q = 0; q < 4; q++) {
            int i = tid + (q << 8);
            int r = i >> 3, c = i & 7;
            uint32_t off = SWZ(r * 128 + c * 16);
            CPA(a_s + off, (const char*)(Ag + (size_t)r * Kp + c * 8));
            CPA(b_s + off, (const char*)(Bg + (size_t)r * Kp + c * 8));
        }
    };

    float acc[2][8][4];
    #pragma unroll
    for (int mt = 0; mt < 2; mt++)
        #pragma unroll
        for (int nt = 0; nt < 8; nt++)
            #pragma unroll
            for (int u = 0; u < 4; u++) acc[mt][nt][u] = 0.f;

    // lane-invariant pieces of ldmatrix addressing
    int j = lane >> 3;                       // matrix id 0..3
    int lrow = lane & 7;
    // A: row += (j&1)*8, byte += (j>>1)*16
    int a_row_off = ((j & 1) << 3) + lrow;
    int a_byte_off = (j >> 1) << 4;
    // B: row += (j>>1)*8, byte += (j&1)*16
    int b_row_off = ((j >> 1) << 3) + lrow;
    int b_byte_off = (j & 1) << 4;

    // prologue
    #pragma unroll
    for (int p = 0; p < S - 1; p++) { load_stage(p, p); CPC(); }

    for (int k = 0; k < nk; k++) {
        CPW(S - 2);
        __syncthreads();
        if (k + S - 1 < nk) load_stage((k + S - 1) % S, k + S - 1);
        CPC();

        uint32_t a_s = sbase + (uint32_t)(k % S) * 32768u;
        uint32_t b_s = a_s + 16384u;
        #pragma unroll
        for (int ks = 0; ks < 4; ks++) {
            uint32_t af[2][4], bf[4][4];
            #pragma unroll
            for (int mt = 0; mt < 2; mt++) {
                int row = warp_m * 32 + mt * 16 + a_row_off;
                int byte = ks * 32 + a_byte_off;
                uint32_t ad = a_s + SWZ(row * 128 + byte);
                LDM_X4(af[mt][0], af[mt][1], af[mt][2], af[mt][3], ad);
            }
            #pragma unroll
            for (int ng = 0; ng < 4; ng++) {
                int row = warp_n * 64 + ng * 16 + b_row_off;
                int byte = ks * 32 + b_byte_off;
                uint32_t bd = b_s + SWZ(row * 128 + byte);
                LDM_X4(bf[ng][0], bf[ng][1], bf[ng][2], bf[ng][3], bd);
            }
            #pragma unroll
            for (int mt = 0; mt < 2; mt++)
                #pragma unroll
                for (int nt = 0; nt < 8; nt++) {
                    uint32_t b0 = bf[nt >> 1][(nt & 1) ? 2 : 0];
                    uint32_t b1 = bf[nt >> 1][(nt & 1) ? 3 : 1];
                    MMA_BF16(acc[mt][nt], af[mt], b0, b1);
                }
        }
        __syncthreads();
    }

    // ---------------- epilogue (register accumulators) ----------------
    int gid = lane >> 2;          // 0..7
    int tig = lane & 3;           // 0..3
    #pragma unroll
    for (int mt = 0; mt < 2; mt++) {
        int m0 = bm + warp_m * 32 + mt * 16 + gid;
        #pragma unroll
        for (int nt = 0; nt < 8; nt++) {
            int n0 = bn + warp_n * 64 + nt * 8 + tig * 2;
            float* ac = acc[mt][nt];
            #pragma unroll
            for (int half = 0; half < 2; half++) {
                int m = m0 + half * 8;
                float v0 = ac[half * 2], v1 = ac[half * 2 + 1];
                if (EPI == 1) {
                    float z0 = v0 + bias[n0], z1 = v1 + bias[n0 + 1];
                    float w0 = (z0 / (1.f + expf(-z0))) * aux0[(size_t)m * 1024 + n0];
                    float w1 = (z1 / (1.f + expf(-z1))) * aux0[(size_t)m * 1024 + n0 + 1];
                    __nv_bfloat16 h0 = __float2bfloat16(w0);
                    __nv_bfloat16 h1 = __float2bfloat16(w1);
                    __nv_bfloat16 l0 = __float2bfloat16(w0 - __bfloat162float(h0));
                    __nv_bfloat16 l1 = __float2bfloat16(w1 - __bfloat162float(h1));
                    size_t ob = (size_t)m * 3072 + n0;
                    *(__nv_bfloat162*)(osplit + ob)        = __nv_bfloat162(h0, h1);
                    *(__nv_bfloat162*)(osplit + ob + 1024) = __nv_bfloat162(l0, l1);
                    *(__nv_bfloat162*)(osplit + ob + 2048) = __nv_bfloat162(h0, h1);
                } else {
                    size_t o = (size_t)m * N + n0;
                    if (EPI == 2) { v0 += bias[n0]; v1 += bias[n0 + 1]; }
                    else if (EPI == 3) {
                        v0 += aux0[o] + aux1[o];
                        v1 += aux0[o + 1] + aux1[o + 1];
                    }
                    float2 w; w.x = v0; w.y = v1;
                    *(float2*)&Cout[o] = w;
                }
            }
        }
    }
}

// ---------------- split helpers ----------------
// SIDE 0 (A): [hi|lo|hi]   SIDE 1 (B): [hi|hi|lo]
template<int SIDE>
__global__ void k_split(const float* __restrict__ in, __nv_bfloat16* __restrict__ out, int K) {
    int idx = blockIdx.x * 256 + threadIdx.x;
    int r = idx / K, k = idx - r * K;
    float v = in[idx];
    __nv_bfloat16 hi = __float2bfloat16(v);
    __nv_bfloat16 lo = __float2bfloat16(v - __bfloat162float(hi));
    size_t b = (size_t)r * 3 * K + k;
    out[b] = hi;
    out[b + K]     = SIDE ? hi : lo;
    out[b + 2 * K] = SIDE ? lo : hi;
}

// ---------------- K1: RMSNorm -> split A directly ----------------
__global__ void k_rmsnorm(const float* __restrict__ x, const float* __restrict__ rms_w) {
    int n = blockIdx.x;
    const float* xr = x + (size_t)n * C_;
    __shared__ float red[256];
    float s = 0.f;
    for (int c = threadIdx.x; c < C_; c += 256) { float v = xr[c]; s += v * v; }
    red[threadIdx.x] = s; __syncthreads();
    for (int o = 128; o > 0; o >>= 1) {
        if (threadIdx.x < o) red[threadIdx.x] += red[threadIdx.x + o];
        __syncthreads();
    }
    float nrm = sqrtf(red[0]) * 0.03125f;
    float inv = 1.0f / fmaxf(nrm, 1e-8f);
    size_t ob = (size_t)n * 3072;
    for (int c = threadIdx.x; c < C_; c += 256) {
        float v = xr[c] * inv * rms_w[c];
        __nv_bfloat16 hi = __float2bfloat16(v);
        __nv_bfloat16 lo = __float2bfloat16(v - __bfloat162float(hi));
        g_a_qkv[ob + c] = hi;
        g_a_qkv[ob + 1024 + c] = lo;
        g_a_qkv[ob + 2048 + c] = hi;
    }
}

// ---------------- K3: xPos rotary (in place on q,k) ----------------
__global__ void k_xpos() {
    int idx = blockIdx.x * 256 + threadIdx.x;
    int n = idx >> 9;
    int j = idx & 511;
    int t = n & (T_ - 1);
    float invf  = powf(10000.0f, -(float)j / 512.0f);
    float theta = (float)t * invf;
    double sd, cd;
    sincos((double)theta, &sd, &cd);
    float svec  = (2.0f * (float)j + 0.4f * 1024.0f) / (1.4f * 1024.0f);
    float pw    = ((float)t - 1024.0f) * (1.0f / 512.0f);
    float scale = powf(svec, pw);
    float cs = (float)cd, sn = (float)sd;
    float cq = cs * scale, sq = sn * scale;
    float ck = cs / scale, sk = sn / scale;
    float* q = g_qkvff + (size_t)n * C5 + 2 * j;
    float* k = q + C_;
    float q0 = q[0], q1 = q[1];
    q[0] = q0 * cq - q1 * sq;  q[1] = q1 * cq + q0 * sq;
    float k0 = k[0], k1 = k[1];
    k[0] = k0 * ck - k1 * sk;  k[1] = k1 * ck + k0 * sk;
}

// ---------------- K4: chunk KV summaries ----------------
__global__ void k_chunk_kv() {
    int blk = blockIdx.x;
    int bh = blk / NC, c = blk % NC;
    int b = bh / H_, h = bh % H_;
    float gamma = 1.0f - exp2f(-5.0f - (float)h);
    __shared__ float Ks[64 * 65], Vs[64 * 65], dec[64];
    for (int i = threadIdx.x; i < HD * HD; i += 256) {
        int j = i >> 6, d = i & 63;
        size_t base = (size_t)(b * T_ + c * HD + j) * C5 + h * HD + d;
        Ks[j * 65 + d] = g_qkvff[base + C_];
        Vs[j * 65 + d] = g_qkvff[base + 2 * C_];
    }
    if (threadIdx.x < 64) dec[threadIdx.x] = powf(gamma, (float)(HD - threadIdx.x));
    __syncthreads();
    float* Wout = g_W + ((size_t)bh * NC + c) * HD * HD;
    for (int i = threadIdx.x; i < HD * HD; i += 256) {
        int d = i >> 6, e = i & 63;
        float s = 0.f;
        #pragma unroll 8
        for (int j = 0; j < 64; j++) s += dec[j] * Ks[j * 65 + d] * Vs[j * 65 + e];
        Wout[i] = s;
    }
}

// ---------------- K5: state scan ----------------
__global__ void k_scan() {
    int bh = blockIdx.x;
    int h = bh % H_;
    float gamma = 1.0f - exp2f(-5.0f - (float)h);
    float g64 = powf(gamma, 64.0f);
    float st[16];
    #pragma unroll
    for (int r = 0; r < 16; r++) st[r] = 0.f;
    size_t base0 = (size_t)bh * NC * 4096;
    for (int c = 0; c < NC; c++) {
        size_t base = base0 + (size_t)c * 4096;
        #pragma unroll
        for (int r = 0; r < 16; r++) {
            int i = threadIdx.x + r * 256;
            g_S[base + i] = st[r];
            st[r] = st[r] * g64 + g_W[base + i];
        }
    }
}

// ---------------- K6: per-chunk attention ----------------
__global__ void k_chunk_attn() {
    extern __shared__ float sm[];
    float* Qs = sm;
    float* Ks = Qs + 64 * 65;
    float* Vs = Ks + 64 * 65;
    float* Ss = Vs + 64 * 65;
    float* As = Ss + 64 * 65;
    int blk = blockIdx.x;
    int bh = blk / NC, c = blk % NC;
    int b = bh / H_, h = bh % H_;
    float gamma = 1.0f - exp2f(-5.0f - (float)h);
    for (int i = threadIdx.x; i < 4096; i += 256) {
        int j = i >> 6, d = i & 63;
        size_t base = (size_t)(b * T_ + c * HD + j) * C5 + h * HD + d;
        Qs[j * 65 + d] = g_qkvff[base];
        Ks[j * 65 + d] = g_qkvff[base + C_];
        Vs[j * 65 + d] = g_qkvff[base + 2 * C_];
        Ss[j * 65 + d] = g_S[((size_t)bh * NC + c) * 4096 + i];
    }
    __syncthreads();
    for (int p = threadIdx.x; p < 4096; p += 256) {
        int i = p >> 6, j = p & 63;
        float s = 0.f;
        if (j <= i) {
            #pragma unroll 8
            for (int d = 0; d < 64; d++) s += Qs[i * 65 + d] * Ks[j * 65 + d];
            s *= powf(gamma, (float)(i - j));
        }
        As[i * 65 + j] = s;
    }
    __syncthreads();
    for (int p = threadIdx.x; p < 4096; p += 256) {
        int i = p >> 6, e = p & 63;
        float acc = 0.f, cr = 0.f;
        #pragma unroll 8
        for (int j = 0; j < 64; j++) {
            acc += As[i * 65 + j] * Vs[j * 65 + e];
            cr  += Qs[i * 65 + j] * Ss[j * 65 + e];
        }
        acc += powf(gamma, (float)i) * cr;
        g_y[(size_t)(b * T_ + c * HD + i) * C_ + h * HD + e] = acc * 0.125f;
    }
}

// ---------------- K7: GroupNorm ----------------
__global__ void k_gn(const float* __restrict__ gn_w, const float* __restrict__ gn_b) {
    int row = blockIdx.x;
    int d = threadIdx.x;
    float* yr = g_y + (size_t)row * 64;
    float a = yr[d], b2 = yr[d + 32];
    float s = a + b2;
    #pragma unroll
    for (int o = 16; o; o >>= 1) s += __shfl_xor_sync(~0u, s, o);
    float mu = s * (1.0f / 64.0f);
    float da = a - mu, db = b2 - mu;
    float ss = da * da + db * db;
    #pragma unroll
    for (int o = 16; o; o >>= 1) ss += __shfl_xor_sync(~0u, ss, o);
    float inv = rsqrtf(ss * (1.0f / 64.0f) + 1e-5f);
    int cb = (row & 15) * 64;
    yr[d]      = da * inv * gn_w[cb + d]      + gn_b[cb + d];
    yr[d + 32] = db * inv * gn_w[cb + d + 32] + gn_b[cb + d + 32];
}

// ---------------- K10: GELU -> split A directly ----------------
__global__ void k_gelu() {
    int idx = blockIdx.x * 256 + threadIdx.x;     // over BT*2C
    int n = idx / (2 * C_);
    int e = idx - n * (2 * C_);
    float v = g_qkvff[(size_t)n * C5 + 3 * C_ + e];
    float g = 0.5f * v * (1.0f + erff(v * 0.70710678118654752f));
    __nv_bfloat16 hi = __float2bfloat16(g);
    __nv_bfloat16 lo = __float2bfloat16(g - __bfloat162float(hi));
    size_t b = (size_t)n * 6144 + e;
    g_a_ff[b] = hi;
    g_a_ff[b + 2048] = lo;
    g_a_ff[b + 4096] = hi;
}

// ---------------- launch ----------------
extern "C" void kernel_launch(void* const* d_in, const int* in_sizes, int n_in,
                              void* d_out, int out_size) {
    const float* x       = (const float*)d_in[0];
    const float* w_qkvff = (const float*)d_in[1];
    const float* w_gated = (const float*)d_in[2];
    const float* b_gated = (const float*)d_in[3];
    const float* w_proj  = (const float*)d_in[4];
    const float* b_proj  = (const float*)d_in[5];
    const float* gn_w    = (const float*)d_in[6];
    const float* gn_b    = (const float*)d_in[7];
    const float* w_ff    = (const float*)d_in[8];
    const float* rms_w   = (const float*)d_in[9];
    float* out = (float*)d_out;

    float *p_qkvff, *p_y, *p_yp;
    __nv_bfloat16 *p_a_qkv, *p_b_qkv, *p_a_x, *p_b_gat, *p_a_prj, *p_b_prj, *p_a_ff, *p_b_ff;
    cudaGetSymbolAddress((void**)&p_qkvff, g_qkvff);
    cudaGetSymbolAddress((void**)&p_y,     g_y);
    cudaGetSymbolAddress((void**)&p_yp,    g_yp);
    cudaGetSymbolAddress((void**)&p_a_qkv, g_a_qkv);
    cudaGetSymbolAddress((void**)&p_b_qkv, g_b_qkv);
    cudaGetSymbolAddress((void**)&p_a_x,   g_a_x);
    cudaGetSymbolAddress((void**)&p_b_gat, g_b_gat);
    cudaGetSymbolAddress((void**)&p_a_prj, g_a_prj);
    cudaGetSymbolAddress((void**)&p_b_prj, g_b_prj);
    cudaGetSymbolAddress((void**)&p_a_ff,  g_a_ff);
    cudaGetSymbolAddress((void**)&p_b_ff,  g_b_ff);

    const int SMEM = 1024 + 4 * 32768;
    cudaFuncSetAttribute(mma_gemm<0>, cudaFuncAttributeMaxDynamicSharedMemorySize, SMEM);
    cudaFuncSetAttribute(mma_gemm<1>, cudaFuncAttributeMaxDynamicSharedMemorySize, SMEM);
    cudaFuncSetAttribute(mma_gemm<2>, cudaFuncAttributeMaxDynamicSharedMemorySize, SMEM);
    cudaFuncSetAttribute(mma_gemm<3>, cudaFuncAttributeMaxDynamicSharedMemorySize, SMEM);
    cudaFuncSetAttribute(k_chunk_attn, cudaFuncAttributeMaxDynamicSharedMemorySize, 5 * 64 * 65 * 4);

    // weight + x splits (independent; run first)
    k_split<1><<<(C5 * C_) / 256, 256>>>(w_qkvff, p_b_qkv, C_);
    k_split<1><<<(C_ * C_) / 256, 256>>>(w_gated, p_b_gat, C_);
    k_split<1><<<(C_ * C_) / 256, 256>>>(w_proj,  p_b_prj, C_);
    k_split<1><<<(C_ * 2 * C_) / 256, 256>>>(w_ff, p_b_ff, 2 * C_);
    k_split<0><<<(BT * C_) / 256, 256>>>(x, p_a_x, C_);

    // 1. RMSNorm (-> split A)
    k_rmsnorm<<<BT, 256>>>(x, rms_w);
    // 2. qkvff GEMM: [4096 x 5120], K'=3072
    mma_gemm<0><<<dim3(C5 / 128, BT / 128), 256, SMEM>>>(
        p_a_qkv, p_b_qkv, 3 * C_, C5, p_qkvff, nullptr, nullptr, nullptr, nullptr);
    // 3. xPos
    k_xpos<<<(BT * 512) / 256, 256>>>();
    // 4-6. chunked retention
    k_chunk_kv<<<BH * NC, 256>>>();
    k_scan<<<BH, 256>>>();
    k_chunk_attn<<<BH * NC, 256, 5 * 64 * 65 * 4>>>();
    // 7. GroupNorm
    k_gn<<<BT * H_, 32>>>(gn_w, gn_b);
    // 8. gate GEMM: silu(x @ w_gated^T + b) * y -> split for proj
    mma_gemm<1><<<dim3(C_ / 128, BT / 128), 256, SMEM>>>(
        p_a_x, p_b_gat, 3 * C_, C_, nullptr, b_gated, p_y, nullptr, p_a_prj);
    // 9. proj GEMM
    mma_gemm<2><<<dim3(C_ / 128, BT / 128), 256, SMEM>>>(
        p_a_prj, p_b_prj, 3 * C_, C_, p_yp, b_proj, nullptr, nullptr, nullptr);
    // 10. GELU (-> split A)
    k_gelu<<<(BT * 2 * C_) / 256, 256>>>();
    // 11. ff GEMM + residuals: out = gelu(ff) @ w_ff^T + x + yp
    mma_gemm<3><<<dim3(C_ / 128, BT / 128), 256, SMEM>>>(
        p_a_ff, p_b_ff, 6 * C_, C_, out, nullptr, x, p_yp, nullptr);
}

// round 4
// speedup vs baseline: 3.1333x; 1.2980x over previous
#include <cuda_runtime.h>
#include <cuda_bf16.h>
#include <math.h>
#include <stdint.h>

#define B_  2
#define T_  2048
#define C_  1024
#define H_  16
#define HD  64
#define BT  (B_*T_)      // 4096
#define C5  (5*C_)       // 5120
#define NC  (T_/HD)      // 32 chunks
#define BH  (B_*H_)      // 32

// ---------------- scratch (device globals) ----------------
__device__ float g_qkvff[BT*(size_t)C5];
__device__ float g_W [BH*(size_t)NC*HD*HD];
__device__ float g_S [BH*(size_t)NC*HD*HD];
__device__ float g_y [BT*(size_t)C_];             // GN'd attention out
__device__ float g_yp[BT*(size_t)C_];             // proj out
// split-bf16 GEMM operands (A: [hi|lo|hi], B: [hi|hi|lo] along K' = 3K)
__device__ __nv_bfloat16 g_a_qkv [BT*(size_t)3*C_];
__device__ __nv_bfloat16 g_b_qkv [C5*(size_t)3*C_];
__device__ __nv_bfloat16 g_a_x   [BT*(size_t)3*C_];
__device__ __nv_bfloat16 g_b_gat [C_*(size_t)3*C_];
__device__ __nv_bfloat16 g_a_prj [BT*(size_t)3*C_];
__device__ __nv_bfloat16 g_b_prj [C_*(size_t)3*C_];
__device__ __nv_bfloat16 g_a_ff  [BT*(size_t)6*C_];
__device__ __nv_bfloat16 g_b_ff  [C_*(size_t)6*C_];

// ---------------- PTX helpers ----------------
__device__ __forceinline__ uint32_t smem_u32(const void* p) {
    uint32_t a;
    asm("{ .reg .u64 t; cvta.to.shared.u64 t, %1; cvt.u32.u64 %0, t; }" : "=r"(a) : "l"(p));
    return a;
}
#define CPA(dst, src)  asm volatile("cp.async.cg.shared.global [%0], [%1], 16;" :: "r"(dst), "l"(src) : "memory")
#define CPC()          asm volatile("cp.async.commit_group;" ::: "memory")
#define CPW(n)         asm volatile("cp.async.wait_group %0;" :: "n"(n) : "memory")
#define SWZ(o) ((o) ^ (((o) >> 3) & 0x70))

#define LDM_X4(r0, r1, r2, r3, a) \
    asm volatile("ldmatrix.sync.aligned.m8n8.x4.shared.b16 {%0,%1,%2,%3}, [%4];" \
        : "=r"(r0), "=r"(r1), "=r"(r2), "=r"(r3) : "r"(a))

#define MMA_BF16(d, a, b0, b1) \
    asm volatile("mma.sync.aligned.m16n8k16.row.col.f32.bf16.bf16.f32 " \
        "{%0,%1,%2,%3}, {%4,%5,%6,%7}, {%8,%9}, {%0,%1,%2,%3};" \
        : "+f"((d)[0]), "+f"((d)[1]), "+f"((d)[2]), "+f"((d)[3]) \
        : "r"((a)[0]), "r"((a)[1]), "r"((a)[2]), "r"((a)[3]), "r"(b0), "r"(b1))

// ---------------- warp-MMA split-bf16 NT GEMM ----------------
// C[M=BT, N] = A'[M, Kp] * B'[N, Kp]^T   (Kp = 3K split encoding)
// block tile 128x256, BK=64, S=4 cp.async stages, 8 warps (2m x 4n), warp 64x64
// EPI 0: Cout=v    1: silu(v+bias[n])*aux0 -> split-bf16 osplit (N=1024)
// EPI 2: v+bias[n] 3: v+aux0+aux1
template<int EPI>
__global__ void __launch_bounds__(256, 1) mma_gemm(
    const __nv_bfloat16* __restrict__ A, const __nv_bfloat16* __restrict__ Bm,
    int Kp, int N, float* __restrict__ Cout,
    const float* __restrict__ bias, const float* __restrict__ aux0,
    const float* __restrict__ aux1, __nv_bfloat16* __restrict__ osplit)
{
    extern __shared__ __align__(1024) char smem_raw[];
    const int S = 4;
    const uint32_t STAGE = 49152;   // A 16KB + B 32KB
    uint32_t sbase = (smem_u32(smem_raw) + 1023) & ~1023u;

    int tid = threadIdx.x;
    int wid = tid >> 5, lane = tid & 31;
    int warp_m = wid & 1, warp_n = wid >> 1;
    int bm = blockIdx.y << 7, bn = blockIdx.x << 8;

    const int nk = Kp >> 6;

    auto load_stage = [&](int s, int k) {
        uint32_t a_s = sbase + s * STAGE;
        uint32_t b_s = a_s + 16384u;
        const __nv_bfloat16* Ag = A + (size_t)bm * Kp + (size_t)k * 64;
        const __nv_bfloat16* Bg = Bm + (size_t)bn * Kp + (size_t)k * 64;
        #pragma unroll
        for (int q = 0; q < 4; q++) {
            int i = tid + (q << 8);
            int r = i >> 3, c = i & 7;
            uint32_t off = SWZ(r * 128 + c * 16);
            CPA(a_s + off, (const char*)(Ag + (size_t)r * Kp + c * 8));
        }
        #pragma unroll
        for (int q = 0; q < 8; q++) {
            int i = tid + (q << 8);
            int r = i >> 3, c = i & 7;
            uint32_t off = SWZ(r * 128 + c * 16);
            CPA(b_s + off, (const char*)(Bg + (size_t)r * Kp + c * 8));
        }
    };

    float acc[4][8][4];
    #pragma unroll
    for (int mt = 0; mt < 4; mt++)
        #pragma unroll
        for (int nt = 0; nt < 8; nt++)
            #pragma unroll
            for (int u = 0; u < 4; u++) acc[mt][nt][u] = 0.f;

    int j = lane >> 3;
    int lrow = lane & 7;
    int a_row_off = ((j & 1) << 3) + lrow;
    int a_byte_off = (j >> 1) << 4;
    int b_row_off = ((j >> 1) << 3) + lrow;
    int b_byte_off = (j & 1) << 4;

    #pragma unroll
    for (int p = 0; p < S - 1; p++) { load_stage(p, p); CPC(); }

    for (int k = 0; k < nk; k++) {
        CPW(S - 2);
        __syncthreads();
        if (k + S - 1 < nk) load_stage((k + S - 1) % S, k + S - 1);
        CPC();

        uint32_t a_s = sbase + (uint32_t)(k % S) * STAGE;
        uint32_t b_s = a_s + 16384u;
        #pragma unroll
        for (int ks = 0; ks < 4; ks++) {
            uint32_t af[4][4], bf[4][4];
            #pragma unroll
            for (int mt = 0; mt < 4; mt++) {
                int row = warp_m * 64 + mt * 16 + a_row_off;
                uint32_t ad = a_s + SWZ(row * 128 + ks * 32 + a_byte_off);
                LDM_X4(af[mt][0], af[mt][1], af[mt][2], af[mt][3], ad);
            }
            #pragma unroll
            for (int ng = 0; ng < 4; ng++) {
                int row = warp_n * 64 + ng * 16 + b_row_off;
                uint32_t bd = b_s + SWZ(row * 128 + ks * 32 + b_byte_off);
                LDM_X4(bf[ng][0], bf[ng][1], bf[ng][2], bf[ng][3], bd);
            }
            #pragma unroll
            for (int mt = 0; mt < 4; mt++)
                #pragma unroll
                for (int nt = 0; nt < 8; nt++) {
                    uint32_t b0 = bf[nt >> 1][(nt & 1) ? 2 : 0];
                    uint32_t b1 = bf[nt >> 1][(nt & 1) ? 3 : 1];
                    MMA_BF16(acc[mt][nt], af[mt], b0, b1);
                }
        }
    }

    // ---------------- epilogue ----------------
    int gid = lane >> 2;
    int tig = lane & 3;
    #pragma unroll
    for (int mt = 0; mt < 4; mt++) {
        int m0 = bm + warp_m * 64 + mt * 16 + gid;
        #pragma unroll
        for (int nt = 0; nt < 8; nt++) {
            int n0 = bn + warp_n * 64 + nt * 8 + tig * 2;
            float* ac = acc[mt][nt];
            #pragma unroll
            for (int half = 0; half < 2; half++) {
                int m = m0 + half * 8;
                float v0 = ac[half * 2], v1 = ac[half * 2 + 1];
                if (EPI == 1) {
                    float z0 = v0 + bias[n0], z1 = v1 + bias[n0 + 1];
                    float w0 = (z0 / (1.f + expf(-z0))) * aux0[(size_t)m * 1024 + n0];
                    float w1 = (z1 / (1.f + expf(-z1))) * aux0[(size_t)m * 1024 + n0 + 1];
                    __nv_bfloat16 h0 = __float2bfloat16(w0);
                    __nv_bfloat16 h1 = __float2bfloat16(w1);
                    __nv_bfloat16 l0 = __float2bfloat16(w0 - __bfloat162float(h0));
                    __nv_bfloat16 l1 = __float2bfloat16(w1 - __bfloat162float(h1));
                    size_t ob = (size_t)m * 3072 + n0;
                    *(__nv_bfloat162*)(osplit + ob)        = __nv_bfloat162(h0, h1);
                    *(__nv_bfloat162*)(osplit + ob + 1024) = __nv_bfloat162(l0, l1);
                    *(__nv_bfloat162*)(osplit + ob + 2048) = __nv_bfloat162(h0, h1);
                } else {
                    size_t o = (size_t)m * N + n0;
                    if (EPI == 2) { v0 += bias[n0]; v1 += bias[n0 + 1]; }
                    else if (EPI == 3) {
                        v0 += aux0[o] + aux1[o];
                        v1 += aux0[o + 1] + aux1[o + 1];
                    }
                    float2 w; w.x = v0; w.y = v1;
                    *(float2*)&Cout[o] = w;
                }
            }
        }
    }
}

// ---------------- split helpers ----------------
template<int SIDE>
__global__ void k_split(const float* __restrict__ in, __nv_bfloat16* __restrict__ out, int K) {
    int idx = blockIdx.x * 256 + threadIdx.x;
    int r = idx / K, k = idx - r * K;
    float v = in[idx];
    __nv_bfloat16 hi = __float2bfloat16(v);
    __nv_bfloat16 lo = __float2bfloat16(v - __bfloat162float(hi));
    size_t b = (size_t)r * 3 * K + k;
    out[b] = hi;
    out[b + K]     = SIDE ? hi : lo;
    out[b + 2 * K] = SIDE ? lo : hi;
}

// ---------------- K1: RMSNorm -> split A ----------------
__global__ void k_rmsnorm(const float* __restrict__ x, const float* __restrict__ rms_w) {
    int n = blockIdx.x;
    const float* xr = x + (size_t)n * C_;
    __shared__ float red[256];
    float s = 0.f;
    for (int c = threadIdx.x; c < C_; c += 256) { float v = xr[c]; s += v * v; }
    red[threadIdx.x] = s; __syncthreads();
    for (int o = 128; o > 0; o >>= 1) {
        if (threadIdx.x < o) red[threadIdx.x] += red[threadIdx.x + o];
        __syncthreads();
    }
    float nrm = sqrtf(red[0]) * 0.03125f;
    float inv = 1.0f / fmaxf(nrm, 1e-8f);
    size_t ob = (size_t)n * 3072;
    for (int c = threadIdx.x; c < C_; c += 256) {
        float v = xr[c] * inv * rms_w[c];
        __nv_bfloat16 hi = __float2bfloat16(v);
        __nv_bfloat16 lo = __float2bfloat16(v - __bfloat162float(hi));
        g_a_qkv[ob + c] = hi;
        g_a_qkv[ob + 1024 + c] = lo;
        g_a_qkv[ob + 2048 + c] = hi;
    }
}

// ---------------- K3: xPos rotary (one thread serves both batches) ----------------
__global__ void k_xpos() {
    int idx = blockIdx.x * 256 + threadIdx.x;        // over T_*512
    int t = idx >> 9;
    int j = idx & 511;
    float invf  = powf(10000.0f, -(float)j / 512.0f);
    float theta = (float)t * invf;
    float sn, cs;
    sincosf(theta, &sn, &cs);
    float svec  = (2.0f * (float)j + 0.4f * 1024.0f) / (1.4f * 1024.0f);
    float pw    = ((float)t - 1024.0f) * (1.0f / 512.0f);
    float scale = powf(svec, pw);
    float cq = cs * scale, sq = sn * scale;
    float ck = cs / scale, sk = sn / scale;
    #pragma unroll
    for (int b = 0; b < 2; b++) {
        float* q = g_qkvff + (size_t)(b * T_ + t) * C5 + 2 * j;
        float* k = q + C_;
        float q0 = q[0], q1 = q[1];
        q[0] = q0 * cq - q1 * sq;  q[1] = q1 * cq + q0 * sq;
        float k0 = k[0], k1 = k[1];
        k[0] = k0 * ck - k1 * sk;  k[1] = k1 * ck + k0 * sk;
    }
}

// ---------------- K4: chunk KV summaries (decay folded, 1x4 blocked) ----------------
__global__ void k_chunk_kv() {
    int blk = blockIdx.x;
    int bh = blk / NC, c = blk % NC;
    int b = bh / H_, h = bh % H_;
    float gamma = 1.0f - exp2f(-5.0f - (float)h);
    __shared__ float Ks[64 * 65], Vs[64 * 64], dec[64];
    if (threadIdx.x < 64) dec[threadIdx.x] = powf(gamma, (float)(HD - threadIdx.x));
    __syncthreads();
    for (int i = threadIdx.x; i < HD * HD; i += 256) {
        int j = i >> 6, d = i & 63;
        size_t base = (size_t)(b * T_ + c * HD + j) * C5 + h * HD + d;
        Ks[j * 65 + d] = g_qkvff[base + C_] * dec[j];
        Vs[j * 64 + d] = g_qkvff[base + 2 * C_];
    }
    __syncthreads();
    float* Wout = g_W + ((size_t)bh * NC + c) * HD * HD;
    for (int p = threadIdx.x; p < 1024; p += 256) {
        int d = p >> 4, e0 = (p & 15) << 2;
        float s0 = 0, s1 = 0, s2 = 0, s3 = 0;
        #pragma unroll 8
        for (int j = 0; j < 64; j++) {
            float kd = Ks[j * 65 + d];
            float4 v4 = *(const float4*)&Vs[j * 64 + e0];
            s0 += kd * v4.x; s1 += kd * v4.y; s2 += kd * v4.z; s3 += kd * v4.w;
        }
        float4 r; r.x = s0; r.y = s1; r.z = s2; r.w = s3;
        *(float4*)&Wout[d * 64 + e0] = r;
    }
}

// ---------------- K5: state scan ----------------
__global__ void k_scan() {
    int bh = blockIdx.x;
    int h = bh % H_;
    float gamma = 1.0f - exp2f(-5.0f - (float)h);
    float g64 = powf(gamma, 64.0f);
    float st[16];
    #pragma unroll
    for (int r = 0; r < 16; r++) st[r] = 0.f;
    size_t base0 = (size_t)bh * NC * 4096;
    for (int c = 0; c < NC; c++) {
        size_t base = base0 + (size_t)c * 4096;
        #pragma unroll
        for (int r = 0; r < 16; r++) {
            int i = threadIdx.x + r * 256;
            g_S[base + i] = st[r];
            st[r] = st[r] * g64 + g_W[base + i];
        }
    }
}

// ---------------- K6: per-chunk attention + fused GroupNorm ----------------
__global__ void k_chunk_attn(const float* __restrict__ gn_w, const float* __restrict__ gn_b) {
    extern __shared__ float sm[];
    float* Qs   = sm;              // 64*65
    float* Kt   = Qs + 64 * 65;    // 64*68 (d-major)
    float* Vs   = Kt + 64 * 68;    // 64*64
    float* Ss   = Vs + 64 * 64;    // 64*64
    float* As   = Ss + 64 * 64;    // 64*68
    float* gpow = As + 64 * 68;    // 64
    int blk = blockIdx.x;
    int bh = blk / NC, c = blk % NC;
    int b = bh / H_, h = bh % H_;
    float gamma = 1.0f - exp2f(-5.0f - (float)h);
    if (threadIdx.x < 64) gpow[threadIdx.x] = powf(gamma, (float)threadIdx.x);
    for (int i = threadIdx.x; i < 4096; i += 256) {
        int j = i >> 6, d = i & 63;
        size_t base = (size_t)(b * T_ + c * HD + j) * C5 + h * HD + d;
        Qs[j * 65 + d] = g_qkvff[base];
        Kt[d * 68 + j] = g_qkvff[base + C_];
        Vs[j * 64 + d] = g_qkvff[base + 2 * C_];
        Ss[i] = g_S[((size_t)bh * NC + c) * 4096 + i];
    }
    __syncthreads();
    // phase 1: masked decayed scores
    for (int p = threadIdx.x; p < 1024; p += 256) {
        int i = p >> 4, j0 = (p & 15) << 2;
        float s0 = 0, s1 = 0, s2 = 0, s3 = 0;
        #pragma unroll 8
        for (int d = 0; d < 64; d++) {
            float q = Qs[i * 65 + d];
            float4 k4 = *(const float4*)&Kt[d * 68 + j0];
            s0 += q * k4.x; s1 += q * k4.y; s2 += q * k4.z; s3 += q * k4.w;
        }
        float4 r;
        r.x = (j0     <= i) ? s0 * gpow[i - j0]     : 0.f;
        r.y = (j0 + 1 <= i) ? s1 * gpow[i - j0 - 1] : 0.f;
        r.z = (j0 + 2 <= i) ? s2 * gpow[i - j0 - 2] : 0.f;
        r.w = (j0 + 3 <= i) ? s3 * gpow[i - j0 - 3] : 0.f;
        *(float4*)&As[i * 68 + j0] = r;
    }
    __syncthreads();
    // phase 2: AV + gamma^i * QS, then fused GroupNorm over hd=64
    for (int p = threadIdx.x; p < 1024; p += 256) {
        int i = p >> 4, e0 = (p & 15) << 2;
        float a0 = 0, a1 = 0, a2 = 0, a3 = 0;
        float c0 = 0, c1 = 0, c2 = 0, c3 = 0;
        #pragma unroll 8
        for (int jj = 0; jj < 64; jj++) {
            float av = As[i * 68 + jj];
            float qv = Qs[i * 65 + jj];
            float4 v4 = *(const float4*)&Vs[jj * 64 + e0];
            float4 s4 = *(const float4*)&Ss[jj * 64 + e0];
            a0 += av * v4.x; a1 += av * v4.y; a2 += av * v4.z; a3 += av * v4.w;
            c0 += qv * s4.x; c1 += qv * s4.y; c2 += qv * s4.z; c3 += qv * s4.w;
        }
        float gi = gpow[i];
        float y0 = (a0 + gi * c0) * 0.125f;
        float y1 = (a1 + gi * c1) * 0.125f;
        float y2 = (a2 + gi * c2) * 0.125f;
        float y3 = (a3 + gi * c3) * 0.125f;
        // GroupNorm: row i is held by 16 consecutive lanes
        float sum = y0 + y1 + y2 + y3;
        float sq  = y0 * y0 + y1 * y1 + y2 * y2 + y3 * y3;
        #pragma unroll
        for (int o = 8; o >= 1; o >>= 1) {
            sum += __shfl_xor_sync(~0u, sum, o);
            sq  += __shfl_xor_sync(~0u, sq, o);
        }
        float mu  = sum * (1.0f / 64.0f);
        float var = sq * (1.0f / 64.0f) - mu * mu;
        float inv = rsqrtf(var + 1e-5f);
        int cb = h * 64 + e0;
        float4 o4;
        o4.x = (y0 - mu) * inv * gn_w[cb]     + gn_b[cb];
        o4.y = (y1 - mu) * inv * gn_w[cb + 1] + gn_b[cb + 1];
        o4.z = (y2 - mu) * inv * gn_w[cb + 2] + gn_b[cb + 2];
        o4.w = (y3 - mu) * inv * gn_w[cb + 3] + gn_b[cb + 3];
        *(float4*)&g_y[(size_t)(b * T_ + c * HD + i) * C_ + cb] = o4;
    }
}

// ---------------- K10: GELU -> split A ----------------
__global__ void k_gelu() {
    int idx = blockIdx.x * 256 + threadIdx.x;
    int n = idx / (2 * C_);
    int e = idx - n * (2 * C_);
    float v = g_qkvff[(size_t)n * C5 + 3 * C_ + e];
    float g = 0.5f * v * (1.0f + erff(v * 0.70710678118654752f));
    __nv_bfloat16 hi = __float2bfloat16(g);
    __nv_bfloat16 lo = __float2bfloat16(g - __bfloat162float(hi));
    size_t b = (size_t)n * 6144 + e;
    g_a_ff[b] = hi;
    g_a_ff[b + 2048] = lo;
    g_a_ff[b + 4096] = hi;
}

// ---------------- launch ----------------
extern "C" void kernel_launch(void* const* d_in, const int* in_sizes, int n_in,
                              void* d_out, int out_size) {
    const float* x       = (const float*)d_in[0];
    const float* w_qkvff = (const float*)d_in[1];
    const float* w_gated = (const float*)d_in[2];
    const float* b_gated = (const float*)d_in[3];
    const float* w_proj  = (const float*)d_in[4];
    const float* b_proj  = (const float*)d_in[5];
    const float* gn_w    = (const float*)d_in[6];
    const float* gn_b    = (const float*)d_in[7];
    const float* w_ff    = (const float*)d_in[8];
    const float* rms_w   = (const float*)d_in[9];
    float* out = (float*)d_out;

    float *p_qkvff, *p_y, *p_yp;
    __nv_bfloat16 *p_a_qkv, *p_b_qkv, *p_a_x, *p_b_gat, *p_a_prj, *p_b_prj, *p_a_ff, *p_b_ff;
    cudaGetSymbolAddress((void**)&p_qkvff, g_qkvff);
    cudaGetSymbolAddress((void**)&p_y,     g_y);
    cudaGetSymbolAddress((void**)&p_yp,    g_yp);
    cudaGetSymbolAddress((void**)&p_a_qkv, g_a_qkv);
    cudaGetSymbolAddress((void**)&p_b_qkv, g_b_qkv);
    cudaGetSymbolAddress((void**)&p_a_x,   g_a_x);
    cudaGetSymbolAddress((void**)&p_b_gat, g_b_gat);
    cudaGetSymbolAddress((void**)&p_a_prj, g_a_prj);
    cudaGetSymbolAddress((void**)&p_b_prj, g_b_prj);
    cudaGetSymbolAddress((void**)&p_a_ff,  g_a_ff);
    cudaGetSymbolAddress((void**)&p_b_ff,  g_b_ff);

    const int SMEM = 1024 + 4 * 49152;               // 197632
    const int ATTN_SMEM = (64*65 + 64*68 + 64*64 + 64*64 + 64*68 + 64) * 4;
    cudaFuncSetAttribute(mma_gemm<0>, cudaFuncAttributeMaxDynamicSharedMemorySize, SMEM);
    cudaFuncSetAttribute(mma_gemm<1>, cudaFuncAttributeMaxDynamicSharedMemorySize, SMEM);
    cudaFuncSetAttribute(mma_gemm<2>, cudaFuncAttributeMaxDynamicSharedMemorySize, SMEM);
    cudaFuncSetAttribute(mma_gemm<3>, cudaFuncAttributeMaxDynamicSharedMemorySize, SMEM);
    cudaFuncSetAttribute(k_chunk_attn, cudaFuncAttributeMaxDynamicSharedMemorySize, ATTN_SMEM);

    // weight + x splits
    k_split<1><<<(C5 * C_) / 256, 256>>>(w_qkvff, p_b_qkv, C_);
    k_split<1><<<(C_ * C_) / 256, 256>>>(w_gated, p_b_gat, C_);
    k_split<1><<<(C_ * C_) / 256, 256>>>(w_proj,  p_b_prj, C_);
    k_split<1><<<(C_ * 2 * C_) / 256, 256>>>(w_ff, p_b_ff, 2 * C_);
    k_split<0><<<(BT * C_) / 256, 256>>>(x, p_a_x, C_);

    // 1. RMSNorm (-> split A)
    k_rmsnorm<<<BT, 256>>>(x, rms_w);
    // 2. qkvff GEMM: [4096 x 5120], K'=3072
    mma_gemm<0><<<dim3(C5 / 256, BT / 128), 256, SMEM>>>(
        p_a_qkv, p_b_qkv, 3 * C_, C5, p_qkvff, nullptr, nullptr, nullptr, nullptr);
    // 3. xPos
    k_xpos<<<(T_ * 512) / 256, 256>>>();
    // 4-6. chunked retention (+ fused GN)
    k_chunk_kv<<<BH * NC, 256>>>();
    k_scan<<<BH, 256>>>();
    k_chunk_attn<<<BH * NC, 256, ATTN_SMEM>>>(gn_w, gn_b);
    // 7. gate GEMM: silu(x @ w_gated^T + b) * y -> split for proj
    mma_gemm<1><<<dim3(C_ / 256, BT / 128), 256, SMEM>>>(
        p_a_x, p_b_gat, 3 * C_, C_, nullptr, b_gated, p_y, nullptr, p_a_prj);
    // 8. proj GEMM
    mma_gemm<2><<<dim3(C_ / 256, BT / 128), 256, SMEM>>>(
        p_a_prj, p_b_prj, 3 * C_, C_, p_yp, b_proj, nullptr, nullptr, nullptr);
    // 9. GELU (-> split A)
    k_gelu<<<(BT * 2 * C_) / 256, 256>>>();
    // 10. ff GEMM + residuals: out = gelu(ff) @ w_ff^T + x + yp
    mma_gemm<3><<<dim3(C_ / 256, BT / 128), 256, SMEM>>>(
        p_a_ff, p_b_ff, 6 * C_, C_, out, nullptr, x, p_yp, nullptr);
}